// round 6
// baseline (speedup 1.0000x reference)
#include <cuda_runtime.h>

// ---------------------------------------------------------------------------
// HourlyWaterQualityPredictor — fused ConvLSTM(12 steps) + decoder, fp32.
// R4: NB=16 batches/CTA, 512 threads; each thread accumulates 2 batches
// (bi8, bi8+8) so each weight LDS feeds 2x the FFMA2 work (ratio 5.7:1).
// Thread (bi8, hp, r): hidden pair {2hp,2hp+1}, row r, batches bi8 & bi8+8.
// Conv weights in smem permuted [k(9)][ic(35)][oc(128)]; decoder scratch
// reuses the weight region after the recurrence.
// ---------------------------------------------------------------------------

#define NB    16
#define NTHR  512
#define ICH   35
#define INS   560             // per-batch floats: 35*16
#define WCNT  (9 * 35 * 128)  // 40320

typedef unsigned long long ull;

__device__ __forceinline__ ull fma2(ull a, ull b, ull c) {
    ull d;
    asm("fma.rn.f32x2 %0, %1, %2, %3;" : "=l"(d) : "l"(a), "l"(b), "l"(c));
    return d;
}
__device__ __forceinline__ ull bcast2(float v) {
    ull d;
    asm("mov.b64 %0, {%1, %1};" : "=l"(d) : "f"(v));
    return d;
}
__device__ __forceinline__ ull pack2(float a, float b) {
    ull d;
    asm("mov.b64 %0, {%1, %2};" : "=l"(d) : "f"(a), "f"(b));
    return d;
}
__device__ __forceinline__ float2 unpack2(ull v) {
    float2 r;
    asm("mov.b64 {%0, %1}, %2;" : "=f"(r.x), "=f"(r.y) : "l"(v));
    return r;
}

__device__ __forceinline__ float sigf(float v) {
    return __fdividef(1.0f, 1.0f + __expf(-v));
}
__device__ __forceinline__ float tanh_fast(float v) {
    v = fminf(fmaxf(v, -15.0f), 15.0f);
    float e = __expf(2.0f * v);
    return __fdividef(e - 1.0f, e + 1.0f);
}

#define GETC(v4, idx) ((idx) == 0 ? (v4).x : (idx) == 1 ? (v4).y : (idx) == 2 ? (v4).z : (v4).w)

extern __shared__ float smem[];

__global__ __launch_bounds__(NTHR, 1)
void wq_fused_kernel(const float* __restrict__ x,      const float* __restrict__ hour,
                     const float* __restrict__ conv_w, const float* __restrict__ conv_b,
                     const float* __restrict__ he_w1,  const float* __restrict__ he_b1,
                     const float* __restrict__ he_w2,  const float* __restrict__ he_b2,
                     const float* __restrict__ d_w1,   const float* __restrict__ d_b1,
                     const float* __restrict__ d_w2,   const float* __restrict__ d_b2,
                     const float* __restrict__ d_w3,   const float* __restrict__ d_b3,
                     float* __restrict__ out, int B)
{
    float* w_s    = smem;             // [9][35][128]; decoder scratch later
    float* b_s    = w_s + WCNT;       // [128]
    float* in_all = b_s + 128;        // [NB][INS]
    float* hf_s   = in_all + NB * INS;// [NB][32]

    const int tid = threadIdx.x;
    const int bi8 = tid >> 6;         // 0..7 -> batches bi8, bi8+8
    const int tib = tid & 63;
    const int hp  = tib >> 2;         // hidden pair 0..15
    const int r   = tib & 3;          // image row
    const int b0  = blockIdx.x * NB;

    // ---- stage conv weights, permuted [k][ic][oc] ----
    for (int s = tid; s < WCNT; s += NTHR) {
        int oc  = s / 315;
        int rem = s - oc * 315;
        int ic  = rem / 9;
        int k   = rem - ic * 9;
        w_s[(k * 35 + ic) * 128 + oc] = conv_w[s];
    }
    for (int s = tid; s < 128; s += NTHR) b_s[s] = conv_b[s];

    // ---- zero state, load x_0 (as float4: 16 batches x 12 vec4) ----
    for (int s = tid; s < NB * INS; s += NTHR) in_all[s] = 0.0f;
    __syncthreads();
    if (tid < NB * 12) {
        int bb = tid / 12, q = tid - bb * 12;
        int gb = b0 + bb;
        if (gb < B)
            *reinterpret_cast<float4*>(in_all + bb * INS + q * 4) =
                *reinterpret_cast<const float4*>(x + (size_t)gb * 576 + q * 4);
    }
    __syncthreads();

    float* inA = in_all + bi8 * INS;
    float* inB = in_all + (bi8 + 8) * INS;
    const float* wb0 = w_s + 2 * hp;

    ull cstA[4], cstB[4];
    #pragma unroll
    for (int p = 0; p < 4; p++) { cstA[p] = 0ULL; cstB[p] = 0ULL; }

    // ---------------------- 12-step ConvLSTM recurrence ----------------------
    #pragma unroll 1
    for (int t = 0; t < 12; ++t) {
        ull acc[2][4][4];   // [batch][gate][px], each = 2 oc packed
        {
            ull bI = *reinterpret_cast<const ull*>(b_s +      2 * hp);
            ull bF = *reinterpret_cast<const ull*>(b_s + 32 + 2 * hp);
            ull bO = *reinterpret_cast<const ull*>(b_s + 64 + 2 * hp);
            ull bG = *reinterpret_cast<const ull*>(b_s + 96 + 2 * hp);
            #pragma unroll
            for (int p = 0; p < 4; p++) {
                acc[0][0][p] = bI; acc[1][0][p] = bI;
                acc[0][1][p] = bF; acc[1][1][p] = bF;
                acc[0][2][p] = bO; acc[1][2][p] = bO;
                acc[0][3][p] = bG; acc[1][3][p] = bG;
            }
        }

        #pragma unroll 1
        for (int ic = 0; ic < ICH; ++ic) {
            const float* rA = inA + ic * 16;
            const float* rB = inB + ic * 16;
            float4 amA = make_float4(0.f,0.f,0.f,0.f), apA = amA;
            float4 amB = amA, apB = amA;
            if (r > 0) { amA = *reinterpret_cast<const float4*>(rA + (r-1)*4);
                         amB = *reinterpret_cast<const float4*>(rB + (r-1)*4); }
            float4 a0A = *reinterpret_cast<const float4*>(rA + r*4);
            float4 a0B = *reinterpret_cast<const float4*>(rB + r*4);
            if (r < 3) { apA = *reinterpret_cast<const float4*>(rA + (r+1)*4);
                         apB = *reinterpret_cast<const float4*>(rB + (r+1)*4); }

            const float* wic = wb0 + ic * 128;
            #pragma unroll
            for (int k = 0; k < 9; ++k) {
                const int dy = k / 3 - 1;
                const int dx = (k % 3) - 1;
                const float* wp2 = wic + k * 4480;
                ull w0 = *reinterpret_cast<const ull*>(wp2);
                ull w1 = *reinterpret_cast<const ull*>(wp2 + 32);
                ull w2 = *reinterpret_cast<const ull*>(wp2 + 64);
                ull w3 = *reinterpret_cast<const ull*>(wp2 + 96);
                #pragma unroll
                for (int p = 0; p < 4; ++p) {
                    const int sx = p + dx;
                    if (sx >= 0 && sx < 4) {
                        float4 rwA = (dy == -1) ? amA : ((dy == 0) ? a0A : apA);
                        float4 rwB = (dy == -1) ? amB : ((dy == 0) ? a0B : apB);
                        ull ua = bcast2(GETC(rwA, sx));
                        ull ub = bcast2(GETC(rwB, sx));
                        acc[0][0][p] = fma2(w0, ua, acc[0][0][p]);
                        acc[1][0][p] = fma2(w0, ub, acc[1][0][p]);
                        acc[0][1][p] = fma2(w1, ua, acc[0][1][p]);
                        acc[1][1][p] = fma2(w1, ub, acc[1][1][p]);
                        acc[0][2][p] = fma2(w2, ua, acc[0][2][p]);
                        acc[1][2][p] = fma2(w2, ub, acc[1][2][p]);
                        acc[0][3][p] = fma2(w3, ua, acc[0][3][p]);
                        acc[1][3][p] = fma2(w3, ub, acc[1][3][p]);
                    }
                }
            }
        }

        // LSTM cell update (registers only), both batches
        float hA[2][4], hB[2][4];
        #pragma unroll
        for (int p = 0; p < 4; p++) {
            float2 vi = unpack2(acc[0][0][p]);
            float2 vf = unpack2(acc[0][1][p]);
            float2 vo = unpack2(acc[0][2][p]);
            float2 vg = unpack2(acc[0][3][p]);
            float2 cp = unpack2(cstA[p]);
            float c0 = sigf(vf.x) * cp.x + sigf(vi.x) * tanh_fast(vg.x);
            float c1 = sigf(vf.y) * cp.y + sigf(vi.y) * tanh_fast(vg.y);
            cstA[p] = pack2(c0, c1);
            hA[0][p] = sigf(vo.x) * tanh_fast(c0);
            hA[1][p] = sigf(vo.y) * tanh_fast(c1);

            vi = unpack2(acc[1][0][p]);
            vf = unpack2(acc[1][1][p]);
            vo = unpack2(acc[1][2][p]);
            vg = unpack2(acc[1][3][p]);
            cp = unpack2(cstB[p]);
            c0 = sigf(vf.x) * cp.x + sigf(vi.x) * tanh_fast(vg.x);
            c1 = sigf(vf.y) * cp.y + sigf(vi.y) * tanh_fast(vg.y);
            cstB[p] = pack2(c0, c1);
            hB[0][p] = sigf(vo.x) * tanh_fast(c0);
            hB[1][p] = sigf(vo.y) * tanh_fast(c1);
        }

        __syncthreads();   // all conv reads of in_all done
        *reinterpret_cast<float4*>(inA + (3 + 2*hp) * 16 + r * 4) =
            make_float4(hA[0][0], hA[0][1], hA[0][2], hA[0][3]);
        *reinterpret_cast<float4*>(inA + (4 + 2*hp) * 16 + r * 4) =
            make_float4(hA[1][0], hA[1][1], hA[1][2], hA[1][3]);
        *reinterpret_cast<float4*>(inB + (3 + 2*hp) * 16 + r * 4) =
            make_float4(hB[0][0], hB[0][1], hB[0][2], hB[0][3]);
        *reinterpret_cast<float4*>(inB + (4 + 2*hp) * 16 + r * 4) =
            make_float4(hB[1][0], hB[1][1], hB[1][2], hB[1][3]);

        if (t < 11) {
            if (tid < NB * 12) {
                int bb = tid / 12, q = tid - bb * 12;
                int gb = b0 + bb;
                if (gb < B)
                    *reinterpret_cast<float4*>(in_all + bb * INS + q * 4) =
                        *reinterpret_cast<const float4*>(x + (size_t)gb * 576 + (t+1) * 48 + q * 4);
            }
        }
        __syncthreads();
    }

    // ------------------------------ decoder ------------------------------
    // 32 threads per batch; scratch z1/z2 reuse the dead conv-weight region.
    const int db   = tid >> 5;        // batch 0..15
    const int dtib = tid & 31;
    const int gb   = b0 + db;
    const bool dv  = (gb < B);
    const int gld  = dv ? gb : 0;

    // hour embedding -> hf_s[db][32]
    {
        float hv  = hour[gld];
        float a = he_b2[dtib];
        #pragma unroll
        for (int k2 = 0; k2 < 16; ++k2) {
            float tt = fmaxf(hv * he_w1[k2] + he_b1[k2], 0.0f);
            a += tt * he_w2[k2 * 32 + dtib];
        }
        hf_s[db * 32 + dtib] = a;
    }
    __syncthreads();

    // L1: 544 -> 256, 8 outputs/thread
    float a1[8];
    {
        const int j0 = dtib * 8;
        #pragma unroll
        for (int q = 0; q < 8; q++) a1[q] = d_b1[j0 + q];
        const float* zz = in_all + db * INS + 48;   // spatial 512
        #pragma unroll 2
        for (int i = 0; i < 512; ++i) {
            float zi = zz[i];
            float4 wa = *reinterpret_cast<const float4*>(d_w1 + i * 256 + j0);
            float4 wb = *reinterpret_cast<const float4*>(d_w1 + i * 256 + j0 + 4);
            a1[0] += zi * wa.x; a1[1] += zi * wa.y; a1[2] += zi * wa.z; a1[3] += zi * wa.w;
            a1[4] += zi * wb.x; a1[5] += zi * wb.y; a1[6] += zi * wb.z; a1[7] += zi * wb.w;
        }
        const float* hz = hf_s + db * 32;
        #pragma unroll 2
        for (int i = 0; i < 32; ++i) {
            float zi = hz[i];
            float4 wa = *reinterpret_cast<const float4*>(d_w1 + (512 + i) * 256 + j0);
            float4 wb = *reinterpret_cast<const float4*>(d_w1 + (512 + i) * 256 + j0 + 4);
            a1[0] += zi * wa.x; a1[1] += zi * wa.y; a1[2] += zi * wa.z; a1[3] += zi * wa.w;
            a1[4] += zi * wb.x; a1[5] += zi * wb.y; a1[6] += zi * wb.z; a1[7] += zi * wb.w;
        }
    }
    float* z1 = w_s;           // [16][256]
    float* z2 = w_s + 4096;    // [16][128]
    __syncthreads();           // weight region now safe to overwrite
    {
        const int j0 = dtib * 8;
        *reinterpret_cast<float4*>(z1 + db * 256 + j0) =
            make_float4(fmaxf(a1[0],0.f), fmaxf(a1[1],0.f), fmaxf(a1[2],0.f), fmaxf(a1[3],0.f));
        *reinterpret_cast<float4*>(z1 + db * 256 + j0 + 4) =
            make_float4(fmaxf(a1[4],0.f), fmaxf(a1[5],0.f), fmaxf(a1[6],0.f), fmaxf(a1[7],0.f));
    }
    __syncthreads();

    // L2: 256 -> 128, 4 outputs/thread
    {
        const int j0 = dtib * 4;
        float a2[4];
        #pragma unroll
        for (int q = 0; q < 4; q++) a2[q] = d_b2[j0 + q];
        const float* zzz = z1 + db * 256;
        #pragma unroll 2
        for (int i = 0; i < 256; ++i) {
            float zi = zzz[i];
            float4 w = *reinterpret_cast<const float4*>(d_w2 + i * 128 + j0);
            a2[0] += zi * w.x; a2[1] += zi * w.y; a2[2] += zi * w.z; a2[3] += zi * w.w;
        }
        *reinterpret_cast<float4*>(z2 + db * 128 + j0) =
            make_float4(fmaxf(a2[0],0.f), fmaxf(a2[1],0.f), fmaxf(a2[2],0.f), fmaxf(a2[3],0.f));
    }
    __syncthreads();

    // L3: 128 -> 30 + sigmoid
    if (dtib < 30 && dv) {
        float a3 = d_b3[dtib];
        const float* zzz = z2 + db * 128;
        #pragma unroll 4
        for (int i = 0; i < 128; ++i)
            a3 += zzz[i] * d_w3[i * 30 + dtib];
        out[(size_t)gb * 30 + dtib] = sigf(a3);
    }
}

extern "C" void kernel_launch(void* const* d_in, const int* in_sizes, int n_in,
                              void* d_out, int out_size)
{
    const float* x      = (const float*)d_in[0];
    const float* hour   = (const float*)d_in[1];
    const float* conv_w = (const float*)d_in[2];
    const float* conv_b = (const float*)d_in[3];
    const float* he_w1  = (const float*)d_in[4];
    const float* he_b1  = (const float*)d_in[5];
    const float* he_w2  = (const float*)d_in[6];
    const float* he_b2  = (const float*)d_in[7];
    const float* d_w1   = (const float*)d_in[8];
    const float* d_b1   = (const float*)d_in[9];
    const float* d_w2   = (const float*)d_in[10];
    const float* d_b2   = (const float*)d_in[11];
    const float* d_w3   = (const float*)d_in[12];
    const float* d_b3   = (const float*)d_in[13];

    const int B    = in_sizes[0] / 576;
    const int grid = (B + NB - 1) / NB;
    const size_t sm = (size_t)(WCNT + 128 + NB * INS + NB * 32) * sizeof(float); // 199,680 B

    cudaFuncSetAttribute(wq_fused_kernel,
                         cudaFuncAttributeMaxDynamicSharedMemorySize, (int)sm);

    wq_fused_kernel<<<grid, NTHR, sm>>>(x, hour, conv_w, conv_b,
                                        he_w1, he_b1, he_w2, he_b2,
                                        d_w1, d_b1, d_w2, d_b2, d_w3, d_b3,
                                        (float*)d_out, B);
}

// round 8
// speedup vs baseline: 1.0294x; 1.0294x over previous
#include <cuda_runtime.h>
#include <cuda_fp16.h>

// ---------------------------------------------------------------------------
// R8: HMMA (mma.sync m16n8k16 fp16) ConvLSTM + fused decoder.
// CTA = 4 batches (n=64), 512 threads = 16 warps.
// Warp (T, nh): oc-tile T (16 rows), n-half nh (32 cols).
// A rows permuted: row r of tile T -> oc = (r>>2)*32 + T*4 + (r&3),
// so lane q<4 holds gates (i,o), lane q>=4 holds (f,g) of the same channel;
// cell completes with shfl.xor(16). c-state in registers.
// B (im2col of h,x) rebuilt in smem each step by scatter; hi + lo fp16 tiles.
// 3 passes: Ahi*Bhi (k<320) + Ahi*Blo + Alo*Bhi (k<256).
// ---------------------------------------------------------------------------

typedef unsigned int u32;
typedef unsigned short u16;

#define NTHR 512
#define NB   4

// smem byte offsets
#define AHI_OFF 0          // 128 x 640B
#define ALO_OFF 81920      // 128 x 512B   (aliased: hfin f32[512][4] after t=11)
#define BHI_OFF 147456     // 64  x 640B
#define BLO_OFF 188416     // 64  x 512B   (aliased: z1/z2 decoder scratch)
#define XS_OFF  221184     // 12*4*48 u16 = 4608B
#define HF_OFF  225792     // 4*32 f32 = 512B
#define SMEM_TOT 226304

static __device__ __forceinline__ u32 sw640(u32 b) { return b ^ ((b >> 3) & 0x70); }
static __device__ __forceinline__ u32 sw512(u32 b) { return b ^ (((b >> 9) & 7) << 4); }

static __device__ __forceinline__ u32 smem_u32(const void* p) {
    u32 a;
    asm("{ .reg .u64 t; cvta.to.shared.u64 t, %1; cvt.u32.u64 %0, t; }" : "=r"(a) : "l"(p));
    return a;
}
static __device__ __forceinline__ float sigf(float v) {
    return __fdividef(1.0f, 1.0f + __expf(-v));
}
static __device__ __forceinline__ float tanh_fast(float v) {
    v = fminf(fmaxf(v, -15.0f), 15.0f);
    float e = __expf(2.0f * v);
    return __fdividef(e - 1.0f, e + 1.0f);
}
static __device__ __forceinline__ void ldsm4(u32& r0, u32& r1, u32& r2, u32& r3, u32 a) {
    asm volatile("ldmatrix.sync.aligned.m8n8.x4.shared.b16 {%0,%1,%2,%3}, [%4];"
        : "=r"(r0), "=r"(r1), "=r"(r2), "=r"(r3) : "r"(a));
}
static __device__ __forceinline__ void mma16816(float* d, u32 a0, u32 a1, u32 a2, u32 a3,
                                                u32 b0, u32 b1) {
    asm volatile("mma.sync.aligned.m16n8k16.row.col.f32.f16.f16.f32 "
        "{%0,%1,%2,%3}, {%4,%5,%6,%7}, {%8,%9}, {%0,%1,%2,%3};"
        : "+f"(d[0]), "+f"(d[1]), "+f"(d[2]), "+f"(d[3])
        : "r"(a0), "r"(a1), "r"(a2), "r"(a3), "r"(b0), "r"(b1));
}

extern __shared__ char smc[];

__global__ __launch_bounds__(NTHR, 1)
void wq_hmma_kernel(const float* __restrict__ x,      const float* __restrict__ hour,
                    const float* __restrict__ conv_w, const float* __restrict__ conv_b,
                    const float* __restrict__ he_w1,  const float* __restrict__ he_b1,
                    const float* __restrict__ he_w2,  const float* __restrict__ he_b2,
                    const float* __restrict__ d_w1,   const float* __restrict__ d_b1,
                    const float* __restrict__ d_w2,   const float* __restrict__ d_b2,
                    const float* __restrict__ d_w3,   const float* __restrict__ d_b3,
                    float* __restrict__ out, int B)
{
    const int tid  = threadIdx.x;
    const int w    = tid >> 5, lane = tid & 31;
    const int T    = w >> 1, nhalf = w & 1;
    const int q    = lane >> 2, j = lane & 3;
    const int b0   = blockIdx.x * NB;
    const u32 sb   = smem_u32(smc);
    u16* xs = (u16*)(smc + XS_OFF);

    // ---------------- prologue: zero B tiles, stage x, build A ----------------
    {
        u32* bz = (u32*)(smc + BHI_OFF);      // BHI 10240 u32 + BLO 8192 u32 contiguous
        for (int e = tid; e < 18432; e += NTHR) bz[e] = 0u;
    }
    for (int e = tid; e < 12 * NB * 48; e += NTHR) {     // 2304
        int t = e / 192, rm = e - t * 192;
        int bb = rm / 48, qq = rm - bb * 48;
        int gb = b0 + bb; if (gb >= B) gb = B - 1;
        xs[e] = __half_as_ushort(__float2half(x[(size_t)gb * 576 + t * 48 + qq]));
    }
    for (int e = tid; e < 128 * 320; e += NTHR) {        // 40960 -> 80/thread
        int R = e / 320, k = e - R * 320;
        int r16 = R & 15, Tt = R >> 4;
        int oc = (r16 >> 2) * 32 + Tt * 4 + (r16 & 3);
        float wv = 0.0f;
        if (k < 288) {
            int tap = k >> 5, ch = k & 31;
            wv = conv_w[oc * 315 + (3 + ch) * 9 + tap];
        } else if (k < 315) {
            int m = k - 288, tap = m / 3, xc = m - 3 * tap;
            wv = conv_w[oc * 315 + xc * 9 + tap];
        }
        u16 hb = __half_as_ushort(__float2half(wv));
        float hf = __half2float(__ushort_as_half(hb));
        *(u16*)(smc + AHI_OFF + sw640((u32)(R * 640 + k * 2))) = hb;
        if (k < 256)
            *(u16*)(smc + ALO_OFF + sw512((u32)(R * 512 + k * 2))) =
                __half_as_ushort(__float2half(wv - hf));
    }
    __syncthreads();

    // x scatter for t=0
    if (tid < NB * 48) {
        int bb = tid / 48, m = tid - bb * 48;
        int xc = m >> 4, sy = (m >> 2) & 3, sx = m & 3;
        u16 hv = xs[bb * 48 + m];
        #pragma unroll
        for (int dy = 0; dy < 3; dy++) {
            int ny = sy + 1 - dy; if (ny < 0 || ny > 3) continue;
            #pragma unroll
            for (int dx = 0; dx < 3; dx++) {
                int nx = sx + 1 - dx; if (nx < 0 || nx > 3) continue;
                int k = 288 + (dy * 3 + dx) * 3 + xc;
                int n2 = bb * 16 + ny * 4 + nx;
                *(u16*)(smc + BHI_OFF + sw640((u32)(n2 * 640 + k * 2))) = hv;
            }
        }
    }

    // per-lane fragment addresses (byte offsets before swizzle)
    const int ra  = T * 16 + (lane & 7) + ((lane >> 3) & 1) * 8;
    const int ka  = ((lane >> 4) & 1) * 16;
    const u32 rawAhi = (u32)(ra * 640 + ka);
    const u32 rawAlo = (u32)(ra * 512 + ka);
    const int rb0 = nhalf * 32 + (lane & 7) + ((lane >> 4) & 1) * 8;
    const int rb1 = rb0 + 16;
    const int kb  = ((lane >> 3) & 1) * 16;
    const u32 rawBh0 = (u32)(rb0 * 640 + kb), rawBh1 = (u32)(rb1 * 640 + kb);
    const u32 rawBl0 = (u32)(rb0 * 512 + kb), rawBl1 = (u32)(rb1 * 512 + kb);

    // bias per lane (rows q and q+8 of this tile)
    const int oc1 = (q >> 2) * 32 + T * 4 + (q & 3);
    const float bi1 = conv_b[oc1], bi2 = conv_b[oc1 + 64];

    float cst[8];
    #pragma unroll
    for (int i = 0; i < 8; i++) cst[i] = 0.0f;

    float* hfin = (float*)(smc + ALO_OFF);

    __syncthreads();

    // ---------------------- 12-step recurrence ----------------------
    #pragma unroll 1
    for (int t = 0; t < 12; ++t) {
        float acc[4][4];
        #pragma unroll
        for (int nf = 0; nf < 4; nf++) {
            acc[nf][0] = bi1; acc[nf][1] = bi1; acc[nf][2] = bi2; acc[nf][3] = bi2;
        }

        #pragma unroll 2
        for (int s = 0; s < 20; ++s) {
            const u32 so = (u32)(s * 32);
            u32 a0, a1, a2, a3, p0, p1, p2, p3, r0, r1, r2, r3;
            ldsm4(a0, a1, a2, a3, sb + AHI_OFF + sw640(rawAhi + so));
            ldsm4(p0, p1, p2, p3, sb + BHI_OFF + sw640(rawBh0 + so));
            ldsm4(r0, r1, r2, r3, sb + BHI_OFF + sw640(rawBh1 + so));
            mma16816(acc[0], a0, a1, a2, a3, p0, p1);
            mma16816(acc[1], a0, a1, a2, a3, p2, p3);
            mma16816(acc[2], a0, a1, a2, a3, r0, r1);
            mma16816(acc[3], a0, a1, a2, a3, r2, r3);
            if (s < 16) {
                u32 l0, l1, l2, l3, m0, m1, m2, m3, n0, n1, n2, n3;
                ldsm4(l0, l1, l2, l3, sb + ALO_OFF + sw512(rawAlo + so));
                ldsm4(m0, m1, m2, m3, sb + BLO_OFF + sw512(rawBl0 + so));
                ldsm4(n0, n1, n2, n3, sb + BLO_OFF + sw512(rawBl1 + so));
                mma16816(acc[0], a0, a1, a2, a3, m0, m1);
                mma16816(acc[1], a0, a1, a2, a3, m2, m3);
                mma16816(acc[2], a0, a1, a2, a3, n0, n1);
                mma16816(acc[3], a0, a1, a2, a3, n2, n3);
                mma16816(acc[0], l0, l1, l2, l3, p0, p1);
                mma16816(acc[1], l0, l1, l2, l3, p2, p3);
                mma16816(acc[2], l0, l1, l2, l3, r0, r1);
                mma16816(acc[3], l0, l1, l2, l3, r2, r3);
            }
        }

        __syncthreads();   // all ldmatrix reads of B done before scatter rewrites

        // ---- cell + scatter ----
        #pragma unroll
        for (int nf = 0; nf < 4; nf++) {
            float rf0 = __shfl_xor_sync(0xFFFFFFFFu, acc[nf][0], 16);
            float rf1 = __shfl_xor_sync(0xFFFFFFFFu, acc[nf][1], 16);
            float rg0 = __shfl_xor_sync(0xFFFFFFFFu, acc[nf][2], 16);
            float rg1 = __shfl_xor_sync(0xFFFFFFFFu, acc[nf][3], 16);
            if (q < 4) {
                const int ch = T * 4 + q;
                #pragma unroll
                for (int cc = 0; cc < 2; cc++) {
                    float gi = acc[nf][cc];
                    float go = acc[nf][2 + cc];
                    float gf = cc ? rf1 : rf0;
                    float gg = cc ? rg1 : rg0;
                    const int ci = nf * 2 + cc;
                    float c = sigf(gf) * cst[ci] + sigf(gi) * tanh_fast(gg);
                    cst[ci] = c;
                    float h = sigf(go) * tanh_fast(c);

                    const int n  = nhalf * 32 + nf * 8 + 2 * j + cc;
                    const int bb = n >> 4, py = (n >> 2) & 3, px = n & 3;
                    if (t < 11) {
                        u16 hv = __half_as_ushort(__float2half(h));
                        float hf = __half2float(__ushort_as_half(hv));
                        u16 lv = __half_as_ushort(__float2half(h - hf));
                        #pragma unroll
                        for (int dy = 0; dy < 3; dy++) {
                            int ny = py + 1 - dy; if (ny < 0 || ny > 3) continue;
                            #pragma unroll
                            for (int dx = 0; dx < 3; dx++) {
                                int nx = px + 1 - dx; if (nx < 0 || nx > 3) continue;
                                int k = (dy * 3 + dx) * 32 + ch;
                                int nn = bb * 16 + ny * 4 + nx;
                                *(u16*)(smc + BHI_OFF + sw640((u32)(nn * 640 + k * 2))) = hv;
                                if (k < 256)
                                    *(u16*)(smc + BLO_OFF + sw512((u32)(nn * 512 + k * 2))) = lv;
                            }
                        }
                    } else {
                        hfin[(ch * 16 + (n & 15)) * 4 + bb] = h;
                    }
                }
            }
        }

        // x scatter for t+1
        if (t < 11 && tid < NB * 48) {
            int bb = tid / 48, m = tid - bb * 48;
            int xc = m >> 4, sy = (m >> 2) & 3, sx = m & 3;
            u16 hv = xs[(t + 1) * 192 + bb * 48 + m];
            #pragma unroll
            for (int dy = 0; dy < 3; dy++) {
                int ny = sy + 1 - dy; if (ny < 0 || ny > 3) continue;
                #pragma unroll
                for (int dx = 0; dx < 3; dx++) {
                    int nx = sx + 1 - dx; if (nx < 0 || nx > 3) continue;
                    int k = 288 + (dy * 3 + dx) * 3 + xc;
                    int n2 = bb * 16 + ny * 4 + nx;
                    *(u16*)(smc + BHI_OFF + sw640((u32)(n2 * 640 + k * 2))) = hv;
                }
            }
        }
        __syncthreads();
    }

    // ------------------------------ decoder ------------------------------
    float* hf_s = (float*)(smc + HF_OFF);
    float* z1   = (float*)(smc + BLO_OFF);          // [256][4]
    float* z2   = (float*)(smc + BLO_OFF + 4096);   // [128][4]
    const int db = tid >> 7, dt = tid & 127;
    const int gb = b0 + db;
    const int gld = (gb < B) ? gb : (B - 1);

    if (dt < 32) {
        float hv = hour[gld];
        float a = he_b2[dt];
        #pragma unroll
        for (int k2 = 0; k2 < 16; ++k2) {
            float tt = fmaxf(hv * he_w1[k2] + he_b1[k2], 0.0f);
            a += tt * he_w2[k2 * 32 + dt];
        }
        hf_s[db * 32 + dt] = a;
    }
    __syncthreads();

    // L1: 544 -> 256, 2 outputs/thread
    {
        const int j0 = dt * 2;
        float a0 = d_b1[j0], a1 = d_b1[j0 + 1];
        #pragma unroll 4
        for (int i = 0; i < 512; ++i) {
            float zi = hfin[i * 4 + db];
            float2 w2 = *(const float2*)(d_w1 + i * 256 + j0);
            a0 += zi * w2.x; a1 += zi * w2.y;
        }
        #pragma unroll 4
        for (int i = 0; i < 32; ++i) {
            float zi = hf_s[db * 32 + i];
            float2 w2 = *(const float2*)(d_w1 + (512 + i) * 256 + j0);
            a0 += zi * w2.x; a1 += zi * w2.y;
        }
        z1[(j0 + 0) * 4 + db] = fmaxf(a0, 0.0f);
        z1[(j0 + 1) * 4 + db] = fmaxf(a1, 0.0f);
    }
    __syncthreads();

    // L2: 256 -> 128, 1 output/thread
    {
        float a = d_b2[dt];
        #pragma unroll 4
        for (int i = 0; i < 256; ++i)
            a += z1[i * 4 + db] * d_w2[i * 128 + dt];
        z2[dt * 4 + db] = fmaxf(a, 0.0f);
    }
    __syncthreads();

    // L3: 128 -> 30 + sigmoid
    if (dt < 30 && gb < B) {
        float a = d_b3[dt];
        #pragma unroll 4
        for (int i = 0; i < 128; ++i)
            a += z2[i * 4 + db] * d_w3[i * 30 + dt];
        out[(size_t)gb * 30 + dt] = sigf(a);
    }
}

extern "C" void kernel_launch(void* const* d_in, const int* in_sizes, int n_in,
                              void* d_out, int out_size)
{
    const float* x      = (const float*)d_in[0];
    const float* hour   = (const float*)d_in[1];
    const float* conv_w = (const float*)d_in[2];
    const float* conv_b = (const float*)d_in[3];
    const float* he_w1  = (const float*)d_in[4];
    const float* he_b1  = (const float*)d_in[5];
    const float* he_w2  = (const float*)d_in[6];
    const float* he_b2  = (const float*)d_in[7];
    const float* d_w1   = (const float*)d_in[8];
    const float* d_b1   = (const float*)d_in[9];
    const float* d_w2   = (const float*)d_in[10];
    const float* d_b2   = (const float*)d_in[11];
    const float* d_w3   = (const float*)d_in[12];
    const float* d_b3   = (const float*)d_in[13];

    const int B    = in_sizes[0] / 576;
    const int grid = (B + NB - 1) / NB;

    cudaFuncSetAttribute(wq_hmma_kernel,
                         cudaFuncAttributeMaxDynamicSharedMemorySize, SMEM_TOT);

    wq_hmma_kernel<<<grid, NTHR, SMEM_TOT>>>(x, hour, conv_w, conv_b,
                                             he_w1, he_b1, he_w2, he_b2,
                                             d_w1, d_b1, d_w2, d_b2, d_w3, d_b3,
                                             (float*)d_out, B);
}

// round 9
// speedup vs baseline: 1.9347x; 1.8794x over previous
#include <cuda_runtime.h>
#include <cuda_fp16.h>

// ---------------------------------------------------------------------------
// R9: HMMA ConvLSTM, 2-pass fp16 (A-hi * B-hi  +  A-hi * B-lo), NB=8.
// CTA = 8 batches (n=128), 512 threads = 16 warps: warp (T, nh) covers
// A-rows [32T,32T+32) x n-cols [32nh, 32nh+32).
// A row permutation: R = 32T + 8g + q  <->  oc = g*32 + (8T+q)  (g=gate).
// => each lane holds all 4 gates of channel ch=8T+q: LSTM fully in-lane.
// B = im2col(h,x) rebuilt in smem each step; hi tile (k<320, pitch 640B)
// + lo tile (h residuals, k<192, pitch 384B, custom XOR swizzle).
// ---------------------------------------------------------------------------

typedef unsigned int u32;
typedef unsigned short u16;

#define NTHR 512
#define NB   8

#define AHI_OFF 0            // 128 x 640B = 81920
#define BHI_OFF 81920        // 128 x 640B = 81920
#define BLO_OFF 163840       // 128 x 384B = 49152 (alias: hfin/z1/z2 decoder)
#define XS_OFF  212992       // 12*8*48 u16 = 9216
#define HF_OFF  222208       // 8*32 f32 = 1024
#define SMEM_TOT 223232

static __device__ __forceinline__ u32 sw640(u32 b) { return b ^ ((b >> 3) & 0x70); }

static __device__ __forceinline__ u32 smem_u32(const void* p) {
    u32 a;
    asm("{ .reg .u64 t; cvta.to.shared.u64 t, %1; cvt.u32.u64 %0, t; }" : "=r"(a) : "l"(p));
    return a;
}
static __device__ __forceinline__ float sigf(float v) {
    return __fdividef(1.0f, 1.0f + __expf(-v));
}
static __device__ __forceinline__ float tanh_fast(float v) {
    v = fminf(fmaxf(v, -15.0f), 15.0f);
    float e = __expf(2.0f * v);
    return __fdividef(e - 1.0f, e + 1.0f);
}
static __device__ __forceinline__ void ldsm4(u32& r0, u32& r1, u32& r2, u32& r3, u32 a) {
    asm volatile("ldmatrix.sync.aligned.m8n8.x4.shared.b16 {%0,%1,%2,%3}, [%4];"
        : "=r"(r0), "=r"(r1), "=r"(r2), "=r"(r3) : "r"(a));
}
static __device__ __forceinline__ void mma16816(float* d, u32 a0, u32 a1, u32 a2, u32 a3,
                                                u32 b0, u32 b1) {
    asm volatile("mma.sync.aligned.m16n8k16.row.col.f32.f16.f16.f32 "
        "{%0,%1,%2,%3}, {%4,%5,%6,%7}, {%8,%9}, {%0,%1,%2,%3};"
        : "+f"(d[0]), "+f"(d[1]), "+f"(d[2]), "+f"(d[3])
        : "r"(a0), "r"(a1), "r"(a2), "r"(a3), "r"(b0), "r"(b1));
}

extern __shared__ char smc[];

__global__ __launch_bounds__(NTHR, 1)
void wq_hmma2_kernel(const float* __restrict__ x,      const float* __restrict__ hour,
                     const float* __restrict__ conv_w, const float* __restrict__ conv_b,
                     const float* __restrict__ he_w1,  const float* __restrict__ he_b1,
                     const float* __restrict__ he_w2,  const float* __restrict__ he_b2,
                     const float* __restrict__ d_w1,   const float* __restrict__ d_b1,
                     const float* __restrict__ d_w2,   const float* __restrict__ d_b2,
                     const float* __restrict__ d_w3,   const float* __restrict__ d_b3,
                     float* __restrict__ out, int B)
{
    const int tid  = threadIdx.x;
    const int w    = tid >> 5, lane = tid & 31;
    const int T    = w >> 2, nh = w & 3;
    const int q    = lane >> 2, j = lane & 3;
    const int b0   = blockIdx.x * NB;
    const u32 sb   = smem_u32(smc);
    u16* xs = (u16*)(smc + XS_OFF);

    // ---------------- prologue ----------------
    {   // zero BHI + BLO (contiguous 131072 B = 32768 u32)
        u32* bz = (u32*)(smc + BHI_OFF);
        #pragma unroll
        for (int i = 0; i < 64; i++) bz[tid + i * NTHR] = 0u;
    }
    for (int e = tid; e < 12 * NB * 48; e += NTHR) {       // 4608
        int t = e / 384, rm = e - t * 384;
        int bb = rm / 48, qq = rm - bb * 48;
        int gb = b0 + bb; if (gb >= B) gb = B - 1;
        xs[e] = __half_as_ushort(__float2half(x[(size_t)gb * 576 + t * 48 + qq]));
    }
    for (int e = tid; e < 128 * 320; e += NTHR) {          // A build: 80/thread
        int R = e / 320, k = e - R * 320;
        int g = (R >> 3) & 3, TT = R >> 5, qq = R & 7;
        int oc = g * 32 + TT * 8 + qq;
        float wv = 0.0f;
        if (k < 288)      wv = conv_w[oc * 315 + (3 + (k & 31)) * 9 + (k >> 5)];
        else if (k < 315) { int m = k - 288; wv = conv_w[oc * 315 + (m % 3) * 9 + (m / 3)]; }
        *(u16*)(smc + AHI_OFF + sw640((u32)(R * 640 + k * 2))) =
            __half_as_ushort(__float2half(wv));
    }
    __syncthreads();

    // x scatter for t=0 (k = 288 + tap*3 + xc, hi tile only)
    if (tid < NB * 48) {
        int bb = tid / 48, m = tid - bb * 48;
        int xc = m >> 4, sy = (m >> 2) & 3, sx = m & 3;
        u16 hv = xs[bb * 48 + m];
        #pragma unroll
        for (int dy = 0; dy < 3; dy++) {
            int ny = sy + 1 - dy; if (ny < 0 || ny > 3) continue;
            #pragma unroll
            for (int dx = 0; dx < 3; dx++) {
                int nx = sx + 1 - dx; if (nx < 0 || nx > 3) continue;
                int k = 288 + (dy * 3 + dx) * 3 + xc;
                int n2 = bb * 16 + ny * 4 + nx;
                *(u16*)(smc + BHI_OFF + sw640((u32)(n2 * 640 + k * 2))) = hv;
            }
        }
    }

    // per-lane fragment raw offsets
    const u32 araw0 = (u32)((32 * T + (lane & 7) + ((lane >> 3) & 1) * 8) * 640
                            + ((lane >> 4) & 1) * 16);
    const u32 araw1 = araw0 + 16 * 640;
    const int rB0   = 32 * nh + (lane & 7) + ((lane >> 4) & 1) * 8;
    const int rB1   = rB0 + 16;
    const u32 kbB   = (u32)(((lane >> 3) & 1) * 16);
    const u32 braw0 = (u32)(rB0 * 640) + kbB;
    const u32 braw1 = (u32)(rB1 * 640) + kbB;
    const u32 xrL   = (u32)((lane & 7) << 4);            // lo-tile XOR term
    const u32 lbase0 = sb + BLO_OFF + (u32)(rB0 * 384);
    const u32 lbase1 = sb + BLO_OFF + (u32)(rB1 * 384);

    // per-lane biases: channel ch = 8T+q, gates i,f,o,g
    const int ch = 8 * T + q;
    const float bI = conv_b[ch], bF = conv_b[32 + ch];
    const float bO = conv_b[64 + ch], bG = conv_b[96 + ch];

    float cst[8];
    #pragma unroll
    for (int i = 0; i < 8; i++) cst[i] = 0.0f;

    float* hfin = (float*)(smc + BLO_OFF);               // [512][8] after t=11

    __syncthreads();

    // ---------------------- 12-step recurrence ----------------------
    #pragma unroll 1
    for (int t = 0; t < 12; ++t) {
        float accA[4][4], accB[4][4];                    // [nf][d]; A-frag0 (i,f), A-frag1 (o,g)
        #pragma unroll
        for (int nf = 0; nf < 4; nf++) {
            accA[nf][0] = bI; accA[nf][1] = bI; accA[nf][2] = bF; accA[nf][3] = bF;
            accB[nf][0] = bO; accB[nf][1] = bO; accB[nf][2] = bG; accB[nf][3] = bG;
        }

        #pragma unroll 2
        for (int s = 0; s < 20; ++s) {
            const u32 so = (u32)(s * 32);
            u32 a0,a1,a2,a3, a4,a5,a6,a7, p0,p1,p2,p3, p4,p5,p6,p7;
            ldsm4(a0,a1,a2,a3, sb + AHI_OFF + sw640(araw0 + so));
            ldsm4(a4,a5,a6,a7, sb + AHI_OFF + sw640(araw1 + so));
            ldsm4(p0,p1,p2,p3, sb + BHI_OFF + sw640(braw0 + so));
            ldsm4(p4,p5,p6,p7, sb + BHI_OFF + sw640(braw1 + so));
            mma16816(accA[0], a0,a1,a2,a3, p0,p1);
            mma16816(accA[1], a0,a1,a2,a3, p2,p3);
            mma16816(accA[2], a0,a1,a2,a3, p4,p5);
            mma16816(accA[3], a0,a1,a2,a3, p6,p7);
            mma16816(accB[0], a4,a5,a6,a7, p0,p1);
            mma16816(accB[1], a4,a5,a6,a7, p2,p3);
            mma16816(accB[2], a4,a5,a6,a7, p4,p5);
            mma16816(accB[3], a4,a5,a6,a7, p6,p7);
            if (s < 12) {                                // lo pass, k < 192
                const u32 kx = (kbB + so) ^ xrL;
                u32 l0,l1,l2,l3, l4,l5,l6,l7;
                ldsm4(l0,l1,l2,l3, lbase0 + kx);
                ldsm4(l4,l5,l6,l7, lbase1 + kx);
                mma16816(accA[0], a0,a1,a2,a3, l0,l1);
                mma16816(accA[1], a0,a1,a2,a3, l2,l3);
                mma16816(accA[2], a0,a1,a2,a3, l4,l5);
                mma16816(accA[3], a0,a1,a2,a3, l6,l7);
                mma16816(accB[0], a4,a5,a6,a7, l0,l1);
                mma16816(accB[1], a4,a5,a6,a7, l2,l3);
                mma16816(accB[2], a4,a5,a6,a7, l4,l5);
                mma16816(accB[3], a4,a5,a6,a7, l6,l7);
            }
        }

        __syncthreads();   // all ldmatrix reads done before scatter rewrites B

        // ---- LSTM cell + scatter (all in-lane; ch = 8T+q) ----
        #pragma unroll
        for (int nf = 0; nf < 4; nf++) {
            #pragma unroll
            for (int cc = 0; cc < 2; cc++) {
                float gi = accA[nf][cc],     gf = accA[nf][2 + cc];
                float go = accB[nf][cc],     gg = accB[nf][2 + cc];
                const int ci = nf * 2 + cc;
                float c = sigf(gf) * cst[ci] + sigf(gi) * tanh_fast(gg);
                cst[ci] = c;
                float h = sigf(go) * tanh_fast(c);

                const int n  = nh * 32 + nf * 8 + 2 * j + cc;
                const int bb = n >> 4, py = (n >> 2) & 3, px = n & 3;
                if (t < 11) {
                    u16 hv = __half_as_ushort(__float2half(h));
                    float hf = __half2float(__ushort_as_half(hv));
                    u16 lv = __half_as_ushort(__float2half(h - hf));
                    #pragma unroll
                    for (int dy = 0; dy < 3; dy++) {
                        int ny = py + 1 - dy; if (ny < 0 || ny > 3) continue;
                        #pragma unroll
                        for (int dx = 0; dx < 3; dx++) {
                            int nx = px + 1 - dx; if (nx < 0 || nx > 3) continue;
                            int tap = dy * 3 + dx;
                            int k = tap * 32 + ch;
                            int n2 = bb * 16 + ny * 4 + nx;
                            *(u16*)(smc + BHI_OFF + sw640((u32)(n2 * 640 + k * 2))) = hv;
                            if (k < 192)
                                *(u16*)(smc + BLO_OFF + n2 * 384
                                        + ((u32)(k * 2) ^ ((u32)(n2 & 7) << 4))) = lv;
                        }
                    }
                } else {
                    hfin[(ch * 16 + (n & 15)) * 8 + bb] = h;
                }
            }
        }

        // x scatter for t+1
        if (t < 11 && tid < NB * 48) {
            int bb = tid / 48, m = tid - bb * 48;
            int xc = m >> 4, sy = (m >> 2) & 3, sx = m & 3;
            u16 hv = xs[(t + 1) * 384 + bb * 48 + m];
            #pragma unroll
            for (int dy = 0; dy < 3; dy++) {
                int ny = sy + 1 - dy; if (ny < 0 || ny > 3) continue;
                #pragma unroll
                for (int dx = 0; dx < 3; dx++) {
                    int nx = sx + 1 - dx; if (nx < 0 || nx > 3) continue;
                    int k = 288 + (dy * 3 + dx) * 3 + xc;
                    int n2 = bb * 16 + ny * 4 + nx;
                    *(u16*)(smc + BHI_OFF + sw640((u32)(n2 * 640 + k * 2))) = hv;
                }
            }
        }
        __syncthreads();
    }

    // ------------------------------ decoder ------------------------------
    float* hf_s = (float*)(smc + HF_OFF);                 // [8][32]
    float* z1   = (float*)(smc + BLO_OFF + 16384);        // [256][8]
    float* z2   = (float*)(smc + BLO_OFF + 24576);        // [128][8]
    const int db = tid >> 6, dt = tid & 63;
    const int gb = b0 + db;
    const int gld = (gb < B) ? gb : (B - 1);

    if (dt < 32) {
        float hv = hour[gld];
        float a = he_b2[dt];
        #pragma unroll
        for (int k2 = 0; k2 < 16; ++k2) {
            float tt = fmaxf(hv * he_w1[k2] + he_b1[k2], 0.0f);
            a += tt * he_w2[k2 * 32 + dt];
        }
        hf_s[db * 32 + dt] = a;
    }
    __syncthreads();

    // L1: 544 -> 256, 4 outputs/thread
    {
        const int j0 = dt * 4;
        float a0 = d_b1[j0], a1 = d_b1[j0 + 1], a2 = d_b1[j0 + 2], a3 = d_b1[j0 + 3];
        #pragma unroll 4
        for (int i = 0; i < 512; ++i) {
            float zi = hfin[i * 8 + db];
            float4 w4 = *(const float4*)(d_w1 + i * 256 + j0);
            a0 += zi * w4.x; a1 += zi * w4.y; a2 += zi * w4.z; a3 += zi * w4.w;
        }
        #pragma unroll 4
        for (int i = 0; i < 32; ++i) {
            float zi = hf_s[db * 32 + i];
            float4 w4 = *(const float4*)(d_w1 + (512 + i) * 256 + j0);
            a0 += zi * w4.x; a1 += zi * w4.y; a2 += zi * w4.z; a3 += zi * w4.w;
        }
        __syncthreads();       // hfin reads done before z1 (distinct region anyway)
        z1[(j0 + 0) * 8 + db] = fmaxf(a0, 0.0f);
        z1[(j0 + 1) * 8 + db] = fmaxf(a1, 0.0f);
        z1[(j0 + 2) * 8 + db] = fmaxf(a2, 0.0f);
        z1[(j0 + 3) * 8 + db] = fmaxf(a3, 0.0f);
    }
    __syncthreads();

    // L2: 256 -> 128, 2 outputs/thread
    {
        const int j0 = dt * 2;
        float a0 = d_b2[j0], a1 = d_b2[j0 + 1];
        #pragma unroll 4
        for (int i = 0; i < 256; ++i) {
            float zi = z1[i * 8 + db];
            float2 w2 = *(const float2*)(d_w2 + i * 128 + j0);
            a0 += zi * w2.x; a1 += zi * w2.y;
        }
        z2[(j0 + 0) * 8 + db] = fmaxf(a0, 0.0f);
        z2[(j0 + 1) * 8 + db] = fmaxf(a1, 0.0f);
    }
    __syncthreads();

    // L3: 128 -> 30 + sigmoid
    if (dt < 30 && gb < B) {
        float a = d_b3[dt];
        #pragma unroll 4
        for (int i = 0; i < 128; ++i)
            a += z2[i * 8 + db] * d_w3[i * 30 + dt];
        out[(size_t)gb * 30 + dt] = sigf(a);
    }
}

extern "C" void kernel_launch(void* const* d_in, const int* in_sizes, int n_in,
                              void* d_out, int out_size)
{
    const float* x      = (const float*)d_in[0];
    const float* hour   = (const float*)d_in[1];
    const float* conv_w = (const float*)d_in[2];
    const float* conv_b = (const float*)d_in[3];
    const float* he_w1  = (const float*)d_in[4];
    const float* he_b1  = (const float*)d_in[5];
    const float* he_w2  = (const float*)d_in[6];
    const float* he_b2  = (const float*)d_in[7];
    const float* d_w1   = (const float*)d_in[8];
    const float* d_b1   = (const float*)d_in[9];
    const float* d_w2   = (const float*)d_in[10];
    const float* d_b2   = (const float*)d_in[11];
    const float* d_w3   = (const float*)d_in[12];
    const float* d_b3   = (const float*)d_in[13];

    const int B    = in_sizes[0] / 576;
    const int grid = (B + NB - 1) / NB;

    cudaFuncSetAttribute(wq_hmma2_kernel,
                         cudaFuncAttributeMaxDynamicSharedMemorySize, SMEM_TOT);

    wq_hmma2_kernel<<<grid, NTHR, SMEM_TOT>>>(x, hour, conv_w, conv_b,
                                              he_w1, he_b1, he_w2, he_b2,
                                              d_w1, d_b1, d_w2, d_b2, d_w3, d_b3,
                                              (float*)d_out, B);
}

// round 10
// speedup vs baseline: 2.4574x; 1.2702x over previous
#include <cuda_runtime.h>
#include <cuda_fp16.h>

// ---------------------------------------------------------------------------
// R10: HMMA ConvLSTM, single-pass pure fp16 (A-hi * B-hi only), NB=8.
// CTA = 8 batches (n=128), 512 threads = 16 warps: warp (T, nh) covers
// A-rows [32T,32T+32) x n-cols [32nh, 32nh+32).
// A row permutation: R = 32T + 8g + q  <->  oc = g*32 + (8T+q)  (g=gate).
// => each lane holds all 4 gates of channel ch=8T+q: LSTM fully in-lane.
// B = im2col(h,x) rebuilt in smem each step by scatter (fp16, k<320,
// pitch 640B, SW128-style swizzle). hfin/z1/z2 alias B after the recurrence.
// ---------------------------------------------------------------------------

typedef unsigned int u32;
typedef unsigned short u16;

#define NTHR 512
#define NB   8

#define AHI_OFF 0            // 128 x 640B = 81920
#define BHI_OFF 81920        // 128 x 640B = 81920 (alias: hfin/z1/z2 after t=11)
#define XS_OFF  163840       // 12*8*48 u16 = 9216
#define HF_OFF  173056       // 8*32 f32 = 1024
#define SMEM_TOT 174080

static __device__ __forceinline__ u32 sw640(u32 b) { return b ^ ((b >> 3) & 0x70); }

static __device__ __forceinline__ u32 smem_u32(const void* p) {
    u32 a;
    asm("{ .reg .u64 t; cvta.to.shared.u64 t, %1; cvt.u32.u64 %0, t; }" : "=r"(a) : "l"(p));
    return a;
}
static __device__ __forceinline__ float sigf(float v) {
    return __fdividef(1.0f, 1.0f + __expf(-v));
}
static __device__ __forceinline__ float tanh_fast(float v) {
    v = fminf(fmaxf(v, -15.0f), 15.0f);
    float e = __expf(2.0f * v);
    return __fdividef(e - 1.0f, e + 1.0f);
}
static __device__ __forceinline__ void ldsm4(u32& r0, u32& r1, u32& r2, u32& r3, u32 a) {
    asm volatile("ldmatrix.sync.aligned.m8n8.x4.shared.b16 {%0,%1,%2,%3}, [%4];"
        : "=r"(r0), "=r"(r1), "=r"(r2), "=r"(r3) : "r"(a));
}
static __device__ __forceinline__ void mma16816(float* d, u32 a0, u32 a1, u32 a2, u32 a3,
                                                u32 b0, u32 b1) {
    asm volatile("mma.sync.aligned.m16n8k16.row.col.f32.f16.f16.f32 "
        "{%0,%1,%2,%3}, {%4,%5,%6,%7}, {%8,%9}, {%0,%1,%2,%3};"
        : "+f"(d[0]), "+f"(d[1]), "+f"(d[2]), "+f"(d[3])
        : "r"(a0), "r"(a1), "r"(a2), "r"(a3), "r"(b0), "r"(b1));
}

extern __shared__ char smc[];

__global__ __launch_bounds__(NTHR, 1)
void wq_hmma3_kernel(const float* __restrict__ x,      const float* __restrict__ hour,
                     const float* __restrict__ conv_w, const float* __restrict__ conv_b,
                     const float* __restrict__ he_w1,  const float* __restrict__ he_b1,
                     const float* __restrict__ he_w2,  const float* __restrict__ he_b2,
                     const float* __restrict__ d_w1,   const float* __restrict__ d_b1,
                     const float* __restrict__ d_w2,   const float* __restrict__ d_b2,
                     const float* __restrict__ d_w3,   const float* __restrict__ d_b3,
                     float* __restrict__ out, int B)
{
    const int tid  = threadIdx.x;
    const int w    = tid >> 5, lane = tid & 31;
    const int T    = w >> 2, nh = w & 3;
    const int q    = lane >> 2, j = lane & 3;
    const int b0   = blockIdx.x * NB;
    const u32 sb   = smem_u32(smc);
    u16* xs = (u16*)(smc + XS_OFF);

    // ---------------- prologue ----------------
    {   // zero BHI (81920 B = 20480 u32)
        u32* bz = (u32*)(smc + BHI_OFF);
        #pragma unroll
        for (int i = 0; i < 40; i++) bz[tid + i * NTHR] = 0u;
    }
    for (int e = tid; e < 12 * NB * 48; e += NTHR) {       // 4608
        int t = e / 384, rm = e - t * 384;
        int bb = rm / 48, qq = rm - bb * 48;
        int gb = b0 + bb; if (gb >= B) gb = B - 1;
        xs[e] = __half_as_ushort(__float2half(x[(size_t)gb * 576 + t * 48 + qq]));
    }
    for (int e = tid; e < 128 * 320; e += NTHR) {          // A build: 80/thread
        int R = e / 320, k = e - R * 320;
        int g = (R >> 3) & 3, TT = R >> 5, qq = R & 7;
        int oc = g * 32 + TT * 8 + qq;
        float wv = 0.0f;
        if (k < 288)      wv = conv_w[oc * 315 + (3 + (k & 31)) * 9 + (k >> 5)];
        else if (k < 315) { int m = k - 288; wv = conv_w[oc * 315 + (m % 3) * 9 + (m / 3)]; }
        *(u16*)(smc + AHI_OFF + sw640((u32)(R * 640 + k * 2))) =
            __half_as_ushort(__float2half(wv));
    }
    __syncthreads();

    // x scatter for t=0 (k = 288 + tap*3 + xc)
    if (tid < NB * 48) {
        int bb = tid / 48, m = tid - bb * 48;
        int xc = m >> 4, sy = (m >> 2) & 3, sx = m & 3;
        u16 hv = xs[bb * 48 + m];
        #pragma unroll
        for (int dy = 0; dy < 3; dy++) {
            int ny = sy + 1 - dy; if (ny < 0 || ny > 3) continue;
            #pragma unroll
            for (int dx = 0; dx < 3; dx++) {
                int nx = sx + 1 - dx; if (nx < 0 || nx > 3) continue;
                int k = 288 + (dy * 3 + dx) * 3 + xc;
                int n2 = bb * 16 + ny * 4 + nx;
                *(u16*)(smc + BHI_OFF + sw640((u32)(n2 * 640 + k * 2))) = hv;
            }
        }
    }

    // per-lane fragment raw offsets
    const u32 araw0 = (u32)((32 * T + (lane & 7) + ((lane >> 3) & 1) * 8) * 640
                            + ((lane >> 4) & 1) * 16);
    const u32 araw1 = araw0 + 16 * 640;
    const int rB0   = 32 * nh + (lane & 7) + ((lane >> 4) & 1) * 8;
    const int rB1   = rB0 + 16;
    const u32 kbB   = (u32)(((lane >> 3) & 1) * 16);
    const u32 braw0 = (u32)(rB0 * 640) + kbB;
    const u32 braw1 = (u32)(rB1 * 640) + kbB;

    // per-lane biases: channel ch = 8T+q, gates i,f,o,g
    const int ch = 8 * T + q;
    const float bI = conv_b[ch], bF = conv_b[32 + ch];
    const float bO = conv_b[64 + ch], bG = conv_b[96 + ch];

    float cst[8];
    #pragma unroll
    for (int i = 0; i < 8; i++) cst[i] = 0.0f;

    float* hfin = (float*)(smc + BHI_OFF);               // [512][8] after t=11

    __syncthreads();

    // ---------------------- 12-step recurrence ----------------------
    #pragma unroll 1
    for (int t = 0; t < 12; ++t) {
        float accA[4][4], accB[4][4];                    // [nf][d]; A-frag0 (i,f), A-frag1 (o,g)
        #pragma unroll
        for (int nf = 0; nf < 4; nf++) {
            accA[nf][0] = bI; accA[nf][1] = bI; accA[nf][2] = bF; accA[nf][3] = bF;
            accB[nf][0] = bO; accB[nf][1] = bO; accB[nf][2] = bG; accB[nf][3] = bG;
        }

        #pragma unroll 2
        for (int s = 0; s < 20; ++s) {
            const u32 so = (u32)(s * 32);
            u32 a0,a1,a2,a3, a4,a5,a6,a7, p0,p1,p2,p3, p4,p5,p6,p7;
            ldsm4(a0,a1,a2,a3, sb + AHI_OFF + sw640(araw0 + so));
            ldsm4(a4,a5,a6,a7, sb + AHI_OFF + sw640(araw1 + so));
            ldsm4(p0,p1,p2,p3, sb + BHI_OFF + sw640(braw0 + so));
            ldsm4(p4,p5,p6,p7, sb + BHI_OFF + sw640(braw1 + so));
            mma16816(accA[0], a0,a1,a2,a3, p0,p1);
            mma16816(accA[1], a0,a1,a2,a3, p2,p3);
            mma16816(accA[2], a0,a1,a2,a3, p4,p5);
            mma16816(accA[3], a0,a1,a2,a3, p6,p7);
            mma16816(accB[0], a4,a5,a6,a7, p0,p1);
            mma16816(accB[1], a4,a5,a6,a7, p2,p3);
            mma16816(accB[2], a4,a5,a6,a7, p4,p5);
            mma16816(accB[3], a4,a5,a6,a7, p6,p7);
        }

        __syncthreads();   // all ldmatrix reads done before scatter rewrites B

        // ---- LSTM cell + scatter (all in-lane; ch = 8T+q) ----
        #pragma unroll
        for (int nf = 0; nf < 4; nf++) {
            #pragma unroll
            for (int cc = 0; cc < 2; cc++) {
                float gi = accA[nf][cc],     gf = accA[nf][2 + cc];
                float go = accB[nf][cc],     gg = accB[nf][2 + cc];
                const int ci = nf * 2 + cc;
                float c = sigf(gf) * cst[ci] + sigf(gi) * tanh_fast(gg);
                cst[ci] = c;
                float h = sigf(go) * tanh_fast(c);

                const int n  = nh * 32 + nf * 8 + 2 * j + cc;
                const int bb = n >> 4, py = (n >> 2) & 3, px = n & 3;
                if (t < 11) {
                    u16 hv = __half_as_ushort(__float2half(h));
                    #pragma unroll
                    for (int dy = 0; dy < 3; dy++) {
                        int ny = py + 1 - dy; if (ny < 0 || ny > 3) continue;
                        #pragma unroll
                        for (int dx = 0; dx < 3; dx++) {
                            int nx = px + 1 - dx; if (nx < 0 || nx > 3) continue;
                            int tap = dy * 3 + dx;
                            int k = tap * 32 + ch;
                            int n2 = bb * 16 + ny * 4 + nx;
                            *(u16*)(smc + BHI_OFF + sw640((u32)(n2 * 640 + k * 2))) = hv;
                        }
                    }
                } else {
                    hfin[(ch * 16 + (n & 15)) * 8 + bb] = h;
                }
            }
        }

        // x scatter for t+1
        if (t < 11 && tid < NB * 48) {
            int bb = tid / 48, m = tid - bb * 48;
            int xc = m >> 4, sy = (m >> 2) & 3, sx = m & 3;
            u16 hv = xs[(t + 1) * 384 + bb * 48 + m];
            #pragma unroll
            for (int dy = 0; dy < 3; dy++) {
                int ny = sy + 1 - dy; if (ny < 0 || ny > 3) continue;
                #pragma unroll
                for (int dx = 0; dx < 3; dx++) {
                    int nx = sx + 1 - dx; if (nx < 0 || nx > 3) continue;
                    int k = 288 + (dy * 3 + dx) * 3 + xc;
                    int n2 = bb * 16 + ny * 4 + nx;
                    *(u16*)(smc + BHI_OFF + sw640((u32)(n2 * 640 + k * 2))) = hv;
                }
            }
        }
        __syncthreads();
    }

    // ------------------------------ decoder ------------------------------
    float* hf_s = (float*)(smc + HF_OFF);                 // [8][32]
    float* z1   = (float*)(smc + BHI_OFF + 16384);        // [256][8]
    float* z2   = (float*)(smc + BHI_OFF + 24576);        // [128][8]
    const int db = tid >> 6, dt = tid & 63;
    const int gb = b0 + db;
    const int gld = (gb < B) ? gb : (B - 1);

    if (dt < 32) {
        float hv = hour[gld];
        float a = he_b2[dt];
        #pragma unroll
        for (int k2 = 0; k2 < 16; ++k2) {
            float tt = fmaxf(hv * he_w1[k2] + he_b1[k2], 0.0f);
            a += tt * he_w2[k2 * 32 + dt];
        }
        hf_s[db * 32 + dt] = a;
    }
    __syncthreads();

    // L1: 544 -> 256, 4 outputs/thread
    {
        const int j0 = dt * 4;
        float a0 = d_b1[j0], a1 = d_b1[j0 + 1], a2 = d_b1[j0 + 2], a3 = d_b1[j0 + 3];
        #pragma unroll 4
        for (int i = 0; i < 512; ++i) {
            float zi = hfin[i * 8 + db];
            float4 w4 = *(const float4*)(d_w1 + i * 256 + j0);
            a0 += zi * w4.x; a1 += zi * w4.y; a2 += zi * w4.z; a3 += zi * w4.w;
        }
        #pragma unroll 4
        for (int i = 0; i < 32; ++i) {
            float zi = hf_s[db * 32 + i];
            float4 w4 = *(const float4*)(d_w1 + (512 + i) * 256 + j0);
            a0 += zi * w4.x; a1 += zi * w4.y; a2 += zi * w4.z; a3 += zi * w4.w;
        }
        __syncthreads();       // hfin reads done before z1 writes (z1 is above hfin)
        z1[(j0 + 0) * 8 + db] = fmaxf(a0, 0.0f);
        z1[(j0 + 1) * 8 + db] = fmaxf(a1, 0.0f);
        z1[(j0 + 2) * 8 + db] = fmaxf(a2, 0.0f);
        z1[(j0 + 3) * 8 + db] = fmaxf(a3, 0.0f);
    }
    __syncthreads();

    // L2: 256 -> 128, 2 outputs/thread
    {
        const int j0 = dt * 2;
        float a0 = d_b2[j0], a1 = d_b2[j0 + 1];
        #pragma unroll 4
        for (int i = 0; i < 256; ++i) {
            float zi = z1[i * 8 + db];
            float2 w2 = *(const float2*)(d_w2 + i * 128 + j0);
            a0 += zi * w2.x; a1 += zi * w2.y;
        }
        z2[(j0 + 0) * 8 + db] = fmaxf(a0, 0.0f);
        z2[(j0 + 1) * 8 + db] = fmaxf(a1, 0.0f);
    }
    __syncthreads();

    // L3: 128 -> 30 + sigmoid
    if (dt < 30 && gb < B) {
        float a = d_b3[dt];
        #pragma unroll 4
        for (int i = 0; i < 128; ++i)
            a += z2[i * 8 + db] * d_w3[i * 30 + dt];
        out[(size_t)gb * 30 + dt] = sigf(a);
    }
}

extern "C" void kernel_launch(void* const* d_in, const int* in_sizes, int n_in,
                              void* d_out, int out_size)
{
    const float* x      = (const float*)d_in[0];
    const float* hour   = (const float*)d_in[1];
    const float* conv_w = (const float*)d_in[2];
    const float* conv_b = (const float*)d_in[3];
    const float* he_w1  = (const float*)d_in[4];
    const float* he_b1  = (const float*)d_in[5];
    const float* he_w2  = (const float*)d_in[6];
    const float* he_b2  = (const float*)d_in[7];
    const float* d_w1   = (const float*)d_in[8];
    const float* d_b1   = (const float*)d_in[9];
    const float* d_w2   = (const float*)d_in[10];
    const float* d_b2   = (const float*)d_in[11];
    const float* d_w3   = (const float*)d_in[12];
    const float* d_b3   = (const float*)d_in[13];

    const int B    = in_sizes[0] / 576;
    const int grid = (B + NB - 1) / NB;

    cudaFuncSetAttribute(wq_hmma3_kernel,
                         cudaFuncAttributeMaxDynamicSharedMemorySize, SMEM_TOT);

    wq_hmma3_kernel<<<grid, NTHR, SMEM_TOT>>>(x, hour, conv_w, conv_b,
                                              he_w1, he_b1, he_w2, he_b2,
                                              d_w1, d_b1, d_w2, d_b2, d_w3, d_b3,
                                              (float*)d_out, B);
}